// round 13
// baseline (speedup 1.0000x reference)
#include <cuda_runtime.h>
#include <cstdint>
#include <math.h>

#define D 512
#define K 5
#define THREADS 192
#define BLOCKS 296    // 2 blocks/SM * 148 -> 12 warps/SM, reg cap 170

typedef unsigned long long ull;

__device__ __forceinline__ ull pack2(float lo, float hi) {
    ull r;
    asm("mov.b64 %0, {%1, %2};" : "=l"(r) : "f"(lo), "f"(hi));
    return r;
}
__device__ __forceinline__ void unpack2(ull v, float& lo, float& hi) {
    asm("mov.b64 {%0, %1}, %2;" : "=f"(lo), "=f"(hi) : "l"(v));
}
__device__ __forceinline__ ull fma2(ull a, ull b, ull c) {
    ull d;
    asm("fma.rn.f32x2 %0, %1, %2, %3;" : "=l"(d) : "l"(a), "l"(b), "l"(c));
    return d;
}
__device__ __forceinline__ ull mul2(ull a, ull b) {
    ull d;
    asm("mul.rn.f32x2 %0, %1, %2;" : "=l"(d) : "l"(a), "l"(b));
    return d;
}

// ---------------------------------------------------------------------------
// Fused kernel, TWO rows per warp-iteration (shared 80-reg weight slice).
//   dist_k = x . w_k + pc2_k  (w = -2*alpha*c; alpha*x^2 cancels in softmax)
//   rec_d  = rinv_d * sum_k mp_k * w_kd    (rinv = -0.5/alpha, shared)
//   pred   = sum_k mp_k * sigmoid(cw_k)
// 12 warps/SM x 2 rows = 24 rows in flight (vs 16) -> more DRAM-queue MLP.
// x loads: 8 x LDG.64.CS per row (streaming, dead after read), prefetched
// one iteration ahead; reduction/softmax chains of the two rows interleave.
//   v2[r][p] = xrow_r[2*lane + 64*(p>>1) + (p&1)]  pairs with  w2[k][p].
// ---------------------------------------------------------------------------
__global__ __launch_bounds__(THREADS, 2) void lfr_fused(
    const float* __restrict__ x,          // (N, D)
    const float* __restrict__ alpha,      // (D,)
    const float* __restrict__ cw,         // (K,)
    const float* __restrict__ cent,       // (K, D)
    float* __restrict__ out_map,          // (N, K)
    float* __restrict__ out_rec,          // (N, D)
    float* __restrict__ out_pred,        // (N,)
    int n_rows)
{
    __shared__ float s_rinv[D];           // -0.5 / alpha_d
    __shared__ float s_swr[K];            // sigmoid(cw_k)

    const int tid  = threadIdx.x;
    const int lane = tid & 31;

    for (int i = tid; i < D; i += THREADS) s_rinv[i] = -0.5f / alpha[i];
    if (tid < K) s_swr[tid] = 1.0f / (1.0f + __expf(-cw[tid]));

    // ---- per-lane invariant setup: packed weights + c2 partials ----
    ull  w2[K][8];      // packed -2*alpha*c  (80 regs, shared by both rows)
    float pc2[K];       // per-lane partial of sum(alpha*c^2)
    {
        float4 a4[4];
        #pragma unroll
        for (int j = 0; j < 4; j++)
            a4[j] = reinterpret_cast<const float4*>(alpha)[lane + j * 32];
        #pragma unroll
        for (int k = 0; k < K; k++) {
            pc2[k] = 0.0f;
            const float4* ck = reinterpret_cast<const float4*>(cent + k * D);
            #pragma unroll
            for (int j = 0; j < 4; j++) {
                const float4 c = ck[lane + j * 32];
                pc2[k] += a4[j].x * c.x * c.x + a4[j].y * c.y * c.y
                        + a4[j].z * c.z * c.z + a4[j].w * c.w * c.w;
                w2[k][2 * j]     = pack2(-2.0f * a4[j].x * c.x, -2.0f * a4[j].y * c.y);
                w2[k][2 * j + 1] = pack2(-2.0f * a4[j].z * c.z, -2.0f * a4[j].w * c.w);
            }
        }
    }
    __syncthreads();

    const int warp_global = (blockIdx.x * THREADS + tid) >> 5;
    const int nwarps      = (BLOCKS * THREADS) >> 5;   // 1776
    const int stride2     = 2 * nwarps;

    // Prime: rows row, row+nwarps (streaming loads; stale slots never consumed)
    ull v2[2][8];
    int row = warp_global;
    if (row < n_rows) {
        const ull* xr = reinterpret_cast<const ull*>(x + (size_t)row * D);
        #pragma unroll
        for (int p = 0; p < 8; p++)
            v2[0][p] = __ldcs(xr + 2 * lane + ((p >> 1) << 6) + (p & 1));
    }
    if (row + nwarps < n_rows) {
        const ull* xr = reinterpret_cast<const ull*>(x + (size_t)(row + nwarps) * D);
        #pragma unroll
        for (int p = 0; p < 8; p++)
            v2[1][p] = __ldcs(xr + 2 * lane + ((p >> 1) << 6) + (p & 1));
    }

    while (row < n_rows) {
        const int  rowB = row + nwarps;
        const bool hasB = rowB < n_rows;

        // ---- distance fma stage: 2 x 40 FFMA2 (interleaved) ----
        ull acc[2][K];
        #pragma unroll
        for (int k = 0; k < K; k++) {
            acc[0][k] = pack2(pc2[k], 0.0f);
            acc[1][k] = acc[0][k];
        }
        #pragma unroll
        for (int p = 0; p < 8; p++) {
            #pragma unroll
            for (int k = 0; k < K; k++) {
                acc[0][k] = fma2(v2[0][p], w2[k][p], acc[0][k]);
                acc[1][k] = fma2(v2[1][p], w2[k][p], acc[1][k]);
            }
        }

        // ---- prefetch next row pair (tail below hides the round-trip) ----
        {
            const int pr0 = row + stride2;
            if (pr0 < n_rows) {
                const ull* xr = reinterpret_cast<const ull*>(x + (size_t)pr0 * D);
                #pragma unroll
                for (int p = 0; p < 8; p++)
                    v2[0][p] = __ldcs(xr + 2 * lane + ((p >> 1) << 6) + (p & 1));
            }
            const int pr1 = pr0 + nwarps;
            if (pr1 < n_rows) {
                const ull* xr = reinterpret_cast<const ull*>(x + (size_t)pr1 * D);
                #pragma unroll
                for (int p = 0; p < 8; p++)
                    v2[1][p] = __ldcs(xr + 2 * lane + ((p >> 1) << 6) + (p & 1));
            }
        }

        // ---- 10 interleaved butterfly chains ----
        float dist[2][K];
        #pragma unroll
        for (int r = 0; r < 2; r++) {
            #pragma unroll
            for (int k = 0; k < K; k++) {
                float lo, hi;
                unpack2(acc[r][k], lo, hi);
                dist[r][k] = lo + hi;
            }
        }
        #pragma unroll
        for (int off = 16; off > 0; off >>= 1) {
            #pragma unroll
            for (int r = 0; r < 2; r++) {
                #pragma unroll
                for (int k = 0; k < K; k++)
                    dist[r][k] += __shfl_xor_sync(0xffffffffu, dist[r][k], off);
            }
        }

        // ---- softmax (both rows, replicated in all lanes) ----
        float mp[2][K];
        #pragma unroll
        for (int r = 0; r < 2; r++) {
            float m = dist[r][0];
            #pragma unroll
            for (int k = 1; k < K; k++) m = fmaxf(m, dist[r][k]);
            float s = 0.0f;
            #pragma unroll
            for (int k = 0; k < K; k++) { mp[r][k] = __expf(dist[r][k] - m); s += mp[r][k]; }
            const float inv = 1.0f / s;
            #pragma unroll
            for (int k = 0; k < K; k++) mp[r][k] *= inv;
        }

        if (lane < K) {
            out_map[(size_t)row * K + lane] = mp[0][lane];
            if (hasB) out_map[(size_t)rowB * K + lane] = mp[1][lane];
        }
        if (lane == 0) {
            float p0 = 0.0f, p1 = 0.0f;
            #pragma unroll
            for (int k = 0; k < K; k++) {
                p0 += mp[0][k] * s_swr[k];
                p1 += mp[1][k] * s_swr[k];
            }
            out_pred[row] = p0;
            if (hasB) out_pred[rowB] = p1;
        }

        // ---- reconstruction (both rows; rinv LDS shared) ----
        ull mpA[K], mpB[K];
        #pragma unroll
        for (int k = 0; k < K; k++) {
            mpA[k] = pack2(mp[0][k], mp[0][k]);
            mpB[k] = pack2(mp[1][k], mp[1][k]);
        }
        float4* orowA = reinterpret_cast<float4*>(out_rec + (size_t)row * D);
        float4* orowB = reinterpret_cast<float4*>(out_rec + (size_t)rowB * D);
        const float4* rinv4 = reinterpret_cast<const float4*>(s_rinv);
        #pragma unroll
        for (int j = 0; j < 4; j++) {
            ull sa0 = mul2(mpA[0], w2[0][2 * j]);
            ull sb0 = mul2(mpA[0], w2[0][2 * j + 1]);
            ull sa1 = mul2(mpB[0], w2[0][2 * j]);
            ull sb1 = mul2(mpB[0], w2[0][2 * j + 1]);
            #pragma unroll
            for (int k = 1; k < K; k++) {
                sa0 = fma2(mpA[k], w2[k][2 * j], sa0);
                sb0 = fma2(mpA[k], w2[k][2 * j + 1], sb0);
                sa1 = fma2(mpB[k], w2[k][2 * j], sa1);
                sb1 = fma2(mpB[k], w2[k][2 * j + 1], sb1);
            }
            const float4 rv = rinv4[lane + j * 32];   // one LDS.128 for both rows
            float t0, t1;
            float4 oA, oB;
            unpack2(sa0, t0, t1); oA.x = t0 * rv.x; oA.y = t1 * rv.y;
            unpack2(sb0, t0, t1); oA.z = t0 * rv.z; oA.w = t1 * rv.w;
            orowA[lane + j * 32] = oA;
            if (hasB) {
                unpack2(sa1, t0, t1); oB.x = t0 * rv.x; oB.y = t1 * rv.y;
                unpack2(sb1, t0, t1); oB.z = t0 * rv.z; oB.w = t1 * rv.w;
                orowB[lane + j * 32] = oB;
            }
        }

        row += stride2;
    }
}

extern "C" void kernel_launch(void* const* d_in, const int* in_sizes, int n_in,
                              void* d_out, int out_size) {
    // metadata order: x, is_protected (unused), alpha_p, classif_w, centroids
    const float* x     = (const float*)d_in[0];
    const float* alpha = (const float*)d_in[2];
    const float* w     = (const float*)d_in[3];
    const float* cent  = (const float*)d_in[4];

    const int n_rows = in_sizes[0] / D;   // 65536

    float* out      = (float*)d_out;
    float* out_map  = out;                              // N*K
    float* out_rec  = out + (size_t)n_rows * K;         // N*D
    float* out_pred = out_rec + (size_t)n_rows * D;     // N

    lfr_fused<<<BLOCKS, THREADS>>>(x, alpha, w, cent, out_map, out_rec, out_pred, n_rows);
}

// round 15
// speedup vs baseline: 1.0409x; 1.0409x over previous
#include <cuda_runtime.h>
#include <cstdint>
#include <math.h>

#define D 512
#define K 5
#define THREADS 256
#define BLOCKS 296    // persistent: 2 blocks/SM * 148

typedef unsigned long long ull;

__device__ __forceinline__ ull pack2(float lo, float hi) {
    ull r;
    asm("mov.b64 %0, {%1, %2};" : "=l"(r) : "f"(lo), "f"(hi));
    return r;
}
__device__ __forceinline__ void unpack2(ull v, float& lo, float& hi) {
    asm("mov.b64 {%0, %1}, %2;" : "=f"(lo), "=f"(hi) : "l"(v));
}
__device__ __forceinline__ ull fma2(ull a, ull b, ull c) {
    ull d;
    asm("fma.rn.f32x2 %0, %1, %2, %3;" : "=l"(d) : "l"(a), "l"(b), "l"(c));
    return d;
}
__device__ __forceinline__ ull mul2(ull a, ull b) {
    ull d;
    asm("mul.rn.f32x2 %0, %1, %2;" : "=l"(d) : "l"(a), "l"(b));
    return d;
}

// ---------------------------------------------------------------------------
// Fully fused kernel (identical to the 42.4us R7 kernel except the warp
// reduction loop nest is swapped so the 5 butterfly chains interleave).
//   dist_k  = x . w_k + pc2_k  (w = -2*alpha*c in regs; alpha*x^2 term is
//             row-constant and cancels in softmax) -> butterfly -> softmax
//   rec_d   = rinv_d * sum_k mp_k * w_kd           (rinv = -0.5/alpha)
//   pred    = sum_k mp_k * sigmoid(cw_k)
// Next row's x prefetched (8 x LDG.64, MLP=8) right after the dist-fma
// stage; the reduce/softmax/rec tail runs under the DRAM round-trip.
//   v2[p] = xr[2*lane + 64*(p>>1) + (p&1)]  pairs with  w2[k][p].
// ---------------------------------------------------------------------------
__global__ __launch_bounds__(THREADS, 2) void lfr_fused(
    const float* __restrict__ x,          // (N, D)
    const float* __restrict__ alpha,      // (D,)
    const float* __restrict__ cw,         // (K,)
    const float* __restrict__ cent,       // (K, D)
    float* __restrict__ out_map,          // (N, K)
    float* __restrict__ out_rec,          // (N, D)
    float* __restrict__ out_pred,         // (N,)
    int n_rows)
{
    __shared__ float s_rinv[D];           // -0.5 / alpha_d
    __shared__ float s_swr[K];            // sigmoid(cw_k)

    const int tid  = threadIdx.x;
    const int lane = tid & 31;

    for (int i = tid; i < D; i += THREADS) s_rinv[i] = -0.5f / alpha[i];
    if (tid < K) s_swr[tid] = 1.0f / (1.0f + __expf(-cw[tid]));

    // ---- per-lane invariant setup: packed weights + c2 partials ----
    ull  w2[K][8];      // packed -2*alpha*c  (80 regs)
    float pc2[K];       // per-lane partial of sum(alpha*c^2)
    {
        float4 a4[4];
        #pragma unroll
        for (int j = 0; j < 4; j++)
            a4[j] = reinterpret_cast<const float4*>(alpha)[lane + j * 32];
        #pragma unroll
        for (int k = 0; k < K; k++) {
            pc2[k] = 0.0f;
            const float4* ck = reinterpret_cast<const float4*>(cent + k * D);
            #pragma unroll
            for (int j = 0; j < 4; j++) {
                const float4 c = ck[lane + j * 32];
                pc2[k] += a4[j].x * c.x * c.x + a4[j].y * c.y * c.y
                        + a4[j].z * c.z * c.z + a4[j].w * c.w * c.w;
                w2[k][2 * j]     = pack2(-2.0f * a4[j].x * c.x, -2.0f * a4[j].y * c.y);
                w2[k][2 * j + 1] = pack2(-2.0f * a4[j].z * c.z, -2.0f * a4[j].w * c.w);
            }
        }
    }
    __syncthreads();

    const int warp_global = (blockIdx.x * THREADS + tid) >> 5;
    const int nwarps      = (BLOCKS * THREADS) >> 5;

    // Prime the pipeline: 8 x LDG.64 (max MLP)
    ull v2[8];
    int row = warp_global;
    if (row < n_rows) {
        const ull* xr = reinterpret_cast<const ull*>(x + (size_t)row * D);
        #pragma unroll
        for (int p = 0; p < 8; p++) v2[p] = xr[2 * lane + ((p >> 1) << 6) + (p & 1)];
    }

    while (row < n_rows) {
        // ---- distance fma stage: consume v2 (40 FFMA2) ----
        ull acc[K];
        #pragma unroll
        for (int k = 0; k < K; k++) acc[k] = pack2(pc2[k], 0.0f);
        #pragma unroll
        for (int p = 0; p < 8; p++) {
            #pragma unroll
            for (int k = 0; k < K; k++)
                acc[k] = fma2(v2[p], w2[k][p], acc[k]);
        }

        // ---- prefetch next row: everything below runs under this latency ----
        const int nrow = row + nwarps;
        if (nrow < n_rows) {
            const ull* xr = reinterpret_cast<const ull*>(x + (size_t)nrow * D);
            #pragma unroll
            for (int p = 0; p < 8; p++) v2[p] = xr[2 * lane + ((p >> 1) << 6) + (p & 1)];
        }

        float dist[K];
        #pragma unroll
        for (int k = 0; k < K; k++) {
            float lo, hi;
            unpack2(acc[k], lo, hi);
            dist[k] = lo + hi;
        }

        // Warp butterfly reduce — INTERLEAVED: 'off' outer so the 5
        // independent chains overlap (total ~130 cyc instead of 5x130).
        #pragma unroll
        for (int off = 16; off > 0; off >>= 1) {
            #pragma unroll
            for (int k = 0; k < K; k++)
                dist[k] += __shfl_xor_sync(0xffffffffu, dist[k], off);
        }

        // Softmax over K=5 (replicated in all lanes)
        float m = dist[0];
        #pragma unroll
        for (int k = 1; k < K; k++) m = fmaxf(m, dist[k]);
        float mp[K];
        float s = 0.0f;
        #pragma unroll
        for (int k = 0; k < K; k++) { mp[k] = __expf(dist[k] - m); s += mp[k]; }
        const float inv = 1.0f / s;
        #pragma unroll
        for (int k = 0; k < K; k++) mp[k] *= inv;

        if (lane < K) out_map[(size_t)row * K + lane] = mp[lane];
        if (lane == 0) {
            float p = 0.0f;
            #pragma unroll
            for (int k = 0; k < K; k++) p += mp[k] * s_swr[k];
            out_pred[row] = p;
        }

        // ---- reconstruction: rec_d = rinv_d * sum_k mp_k * w_kd ----
        ull mp2[K];
        #pragma unroll
        for (int k = 0; k < K; k++) mp2[k] = pack2(mp[k], mp[k]);

        float4* orow = reinterpret_cast<float4*>(out_rec + (size_t)row * D);
        const float4* rinv4 = reinterpret_cast<const float4*>(s_rinv);
        #pragma unroll
        for (int j = 0; j < 4; j++) {
            ull sa = mul2(mp2[0], w2[0][2 * j]);
            ull sb = mul2(mp2[0], w2[0][2 * j + 1]);
            #pragma unroll
            for (int k = 1; k < K; k++) {
                sa = fma2(mp2[k], w2[k][2 * j], sa);
                sb = fma2(mp2[k], w2[k][2 * j + 1], sb);
            }
            const float4 rv = rinv4[lane + j * 32];
            float4 o;
            float t0, t1;
            unpack2(sa, t0, t1);
            o.x = t0 * rv.x; o.y = t1 * rv.y;
            unpack2(sb, t0, t1);
            o.z = t0 * rv.z; o.w = t1 * rv.w;
            orow[lane + j * 32] = o;
        }

        row = nrow;
    }
}

extern "C" void kernel_launch(void* const* d_in, const int* in_sizes, int n_in,
                              void* d_out, int out_size) {
    // metadata order: x, is_protected (unused), alpha_p, classif_w, centroids
    const float* x     = (const float*)d_in[0];
    const float* alpha = (const float*)d_in[2];
    const float* w     = (const float*)d_in[3];
    const float* cent  = (const float*)d_in[4];

    const int n_rows = in_sizes[0] / D;   // 65536

    float* out      = (float*)d_out;
    float* out_map  = out;                              // N*K
    float* out_rec  = out + (size_t)n_rows * K;         // N*D
    float* out_pred = out_rec + (size_t)n_rows * D;     // N

    lfr_fused<<<BLOCKS, THREADS>>>(x, alpha, w, cent, out_map, out_rec, out_pred, n_rows);
}